// round 11
// baseline (speedup 1.0000x reference)
#include <cuda_runtime.h>
#include <cuda_fp16.h>
#include <math.h>

#define NMAX   100000
#define NSTR   100096
#define EMAX   1000000
#define HDIM   64
#define NGRAPH 128
#define NCLS   5
#define NBLK   148
#define NTHR   1024

typedef unsigned long long u64;

// ---------------- scratch (device globals; never passed from host) ----------------
__device__ int    g_deg[NMAX];              // statically zero; self-zeroed each run
__device__ int    g_cursor[NMAX];
__device__ int    g_off[NMAX + 1];
__device__ int    g_bsum[NBLK];
__device__ int    g_barcount;
__device__ volatile int g_bargen;
__device__ int    g_poolctr;
__device__ float  g_dinv[NMAX];
__device__ int    g_csrc[EMAX];
__device__ __align__(16) float  g_xs[NMAX * 2];
__device__ __align__(16) float4 g_ax4[NMAX];
__device__ __align__(16) float  g_bufA[(size_t)HDIM * NSTR];  // t2 transposed; later h3 rows
__device__ __align__(16) unsigned char g_buf8[(size_t)NMAX * HDIM]; // g2s in fp8 e4m3
__device__ __align__(16) float  g_pooled[NGRAPH * HDIM];

// ---------------- packed helpers ----------------
__device__ __forceinline__ u64 pack2(float a, float b) {
    u64 r; asm("mov.b64 %0, {%1, %2};" : "=l"(r) : "f"(a), "f"(b)); return r;
}
__device__ __forceinline__ void unpack2(u64 v, float& a, float& b) {
    asm("mov.b64 {%0, %1}, %2;" : "=f"(a), "=f"(b) : "l"(v));
}
__device__ __forceinline__ void fma2(u64& d, u64 a, u64 b, u64 c) {
    asm("fma.rn.f32x2 %0, %1, %2, %3;" : "=l"(d) : "l"(a), "l"(b), "l"(c));
}
// pack (lo, hi) -> e4m3x2, lo in the low byte
__device__ __forceinline__ unsigned short fp8pack2(float lo, float hi) {
    unsigned short r;
    asm("cvt.rn.satfinite.e4m3x2.f32 %0, %1, %2;" : "=h"(r) : "f"(hi), "f"(lo));
    return r;
}
// e4m3x2 -> float2 (low byte -> .x)
__device__ __forceinline__ float2 fp8unpack2(unsigned short v) {
    unsigned h2;
    asm("cvt.rn.f16x2.e4m3x2 %0, %1;" : "=r"(h2) : "h"(v));
    return __half22float2(*(__half2*)&h2);
}

// ---------------- grid barrier (all NBLK blocks resident by construction) -------
__device__ __forceinline__ void gridbar() {
    __syncthreads();
    if (threadIdx.x == 0) {
        __threadfence();
        int g = g_bargen;
        if (atomicAdd(&g_barcount, 1) == NBLK - 1) {
            g_barcount = 0;
            __threadfence();
            g_bargen = g + 1;
        } else {
            while (g_bargen == g) __nanosleep(64);
            __threadfence();
        }
    }
    __syncthreads();
}

// ---------------- cooperative CSR build: count + scan + scatter -----------------
__global__ void __launch_bounds__(NTHR, 1)
k_csr(const float* __restrict__ x, const int* __restrict__ ei, int n, int e, int vec4) {
    __shared__ int ws[32];
    __shared__ int sprefix;
    const int t = threadIdx.x, b = blockIdx.x;
    const int gthread = b * NTHR + t;
    const int gstride = NBLK * NTHR;
    const int lane = t & 31, wid = t >> 5;

    // P1: degree count
    if (vec4) {
        const int4* d4 = (const int4*)(ei + e);
        int n4 = e >> 2;
        for (int i = gthread; i < n4; i += gstride) {
            int4 d = __ldg(&d4[i]);
            atomicAdd(&g_deg[d.x], 1);
            atomicAdd(&g_deg[d.y], 1);
            atomicAdd(&g_deg[d.z], 1);
            atomicAdd(&g_deg[d.w], 1);
        }
    } else {
        for (int i = gthread; i < e; i += gstride)
            atomicAdd(&g_deg[__ldg(&ei[e + i])], 1);
    }
    gridbar();

    // P2: per-chunk scan + dinv + xs + deg rezero
    const int i_scan = (b << 10) + t;
    int xoff = 0, myv = 0;
    {
        int v = (i_scan < n) ? g_deg[i_scan] : 0;
        myv = v;
        if (i_scan < n) {
            g_deg[i_scan] = 0;                       // re-arm for next replay
            float dv = rsqrtf((float)(v + 1));       // +1 self-loop
            g_dinv[i_scan] = dv;
            float2 xv = *(const float2*)(x + 2 * i_scan);
            g_xs[2 * i_scan]     = dv * xv.x;
            g_xs[2 * i_scan + 1] = dv * xv.y;
        }
        int xacc = v;
        #pragma unroll
        for (int o = 1; o < 32; o <<= 1) {
            int y = __shfl_up_sync(0xffffffffu, xacc, o);
            if (lane >= o) xacc += y;
        }
        if (lane == 31) ws[wid] = xacc;
        __syncthreads();
        if (wid == 0) {
            int s = ws[lane];
            #pragma unroll
            for (int o = 1; o < 32; o <<= 1) {
                int y = __shfl_up_sync(0xffffffffu, s, o);
                if (lane >= o) s += y;
            }
            ws[lane] = s;
        }
        __syncthreads();
        int warpoff = (wid == 0) ? 0 : ws[wid - 1];
        xoff = warpoff + xacc - v;
        if (t == 0) g_bsum[b] = ws[31];
    }
    gridbar();

    // P3: chunk-prefix fixup -> off, cursor, sentinel
    {
        if (t < 32) {
            int sum = 0;
            for (int p = t; p < b; p += 32) sum += g_bsum[p];
            #pragma unroll
            for (int o = 16; o; o >>= 1) sum += __shfl_xor_sync(0xffffffffu, sum, o);
            if (t == 0) sprefix = sum;
        }
        __syncthreads();
        if (i_scan < n) {
            int off = sprefix + xoff;
            g_off[i_scan] = off;
            g_cursor[i_scan] = off;
            if (i_scan == n - 1) g_off[n] = off + myv;
        }
    }
    gridbar();

    // P4: scatter
    if (vec4) {
        int n4 = e >> 2;
        const int4* s4 = (const int4*)ei;
        const int4* d4 = (const int4*)(ei + e);
        for (int i = gthread; i < n4; i += gstride) {
            int4 s = __ldg(&s4[i]);
            int4 d = __ldg(&d4[i]);
            int p0 = atomicAdd(&g_cursor[d.x], 1);
            int p1 = atomicAdd(&g_cursor[d.y], 1);
            int p2 = atomicAdd(&g_cursor[d.z], 1);
            int p3 = atomicAdd(&g_cursor[d.w], 1);
            g_csrc[p0] = s.x; g_csrc[p1] = s.y;
            g_csrc[p2] = s.z; g_csrc[p3] = s.w;
        }
    } else {
        for (int i = gthread; i < e; i += gstride) {
            int s = __ldg(&ei[i]), d = __ldg(&ei[e + i]);
            int p = atomicAdd(&g_cursor[d], 1);
            g_csrc[p] = s;
        }
    }
}

// ---------------- layer 1: gather-sum of prescaled xs ----------------
__global__ void k_agg2(int n) {
    int v = blockIdx.x * blockDim.x + threadIdx.x;
    if (v >= n) return;
    int st = g_off[v], en = g_off[v + 1];
    float ax = 0.f, ay = 0.f;
    for (int j = st; j < en; j += 4) {
        int rem = en - j;
        int s0 = __ldg(&g_csrc[j]);
        int s1 = (rem > 1) ? __ldg(&g_csrc[j + 1]) : s0;
        int s2 = (rem > 2) ? __ldg(&g_csrc[j + 2]) : s0;
        int s3 = (rem > 3) ? __ldg(&g_csrc[j + 3]) : s0;
        float2 x0 = *(const float2*)(g_xs + 2 * s0);
        float2 x1 = *(const float2*)(g_xs + 2 * s1);
        float2 x2 = *(const float2*)(g_xs + 2 * s2);
        float2 x3 = *(const float2*)(g_xs + 2 * s3);
        float m1 = (rem > 1) ? 1.f : 0.f;
        float m2 = (rem > 2) ? 1.f : 0.f;
        float m3 = (rem > 3) ? 1.f : 0.f;
        ax += x0.x; ay += x0.y;
        ax = fmaf(m1, x1.x, ax); ay = fmaf(m1, x1.y, ay);
        ax = fmaf(m2, x2.x, ax); ay = fmaf(m2, x2.y, ay);
        ax = fmaf(m3, x3.x, ax); ay = fmaf(m3, x3.y, ay);
    }
    float dv = g_dinv[v];
    ax += g_xs[2 * v];
    ay += g_xs[2 * v + 1];
    float4 o; o.x = dv * ax; o.y = dv * ay; o.z = dv; o.w = 0.f;
    g_ax4[v] = o;
}

// ---------------- layer 2 aggregation with lin1 fused (transposed out) ----------
__global__ void k_l2agg(const float* __restrict__ W1, const float* __restrict__ b1, int n) {
    __shared__ float sT[64 * 9];
    int t = threadIdx.x, wid = t >> 5, lane = t & 31;
    int v = blockIdx.x * 8 + wid;
    float w1x0 = W1[lane],      w1y0 = W1[64 + lane],  bb0 = b1[lane];
    float w1x1 = W1[lane + 32], w1y1 = W1[96 + lane],  bb1 = b1[lane + 32];
    float a0 = 0.f, a1 = 0.f;
    if (v < n) {
        int st = g_off[v], en = g_off[v + 1];
        for (int j = st; j < en; j += 4) {
            int rem = en - j;
            int s0 = __ldg(&g_csrc[j]);
            int s1 = (rem > 1) ? __ldg(&g_csrc[j + 1]) : s0;
            int s2 = (rem > 2) ? __ldg(&g_csrc[j + 2]) : s0;
            int s3 = (rem > 3) ? __ldg(&g_csrc[j + 3]) : s0;
            float4 q0 = g_ax4[s0];
            float4 q1 = g_ax4[s1];
            float4 q2 = g_ax4[s2];
            float4 q3 = g_ax4[s3];
            float m1 = (rem > 1) ? 1.f : 0.f;
            float m2 = (rem > 2) ? 1.f : 0.f;
            float m3 = (rem > 3) ? 1.f : 0.f;
            float h;
            h = fmaxf(fmaf(q0.x, w1x0, fmaf(q0.y, w1y0, bb0)), 0.f); a0 = fmaf(q0.z, h, a0);
            h = fmaxf(fmaf(q0.x, w1x1, fmaf(q0.y, w1y1, bb1)), 0.f); a1 = fmaf(q0.z, h, a1);
            h = fmaxf(fmaf(q1.x, w1x0, fmaf(q1.y, w1y0, bb0)), 0.f); a0 = fmaf(m1 * q1.z, h, a0);
            h = fmaxf(fmaf(q1.x, w1x1, fmaf(q1.y, w1y1, bb1)), 0.f); a1 = fmaf(m1 * q1.z, h, a1);
            h = fmaxf(fmaf(q2.x, w1x0, fmaf(q2.y, w1y0, bb0)), 0.f); a0 = fmaf(m2 * q2.z, h, a0);
            h = fmaxf(fmaf(q2.x, w1x1, fmaf(q2.y, w1y1, bb1)), 0.f); a1 = fmaf(m2 * q2.z, h, a1);
            h = fmaxf(fmaf(q3.x, w1x0, fmaf(q3.y, w1y0, bb0)), 0.f); a0 = fmaf(m3 * q3.z, h, a0);
            h = fmaxf(fmaf(q3.x, w1x1, fmaf(q3.y, w1y1, bb1)), 0.f); a1 = fmaf(m3 * q3.z, h, a1);
        }
        float4 q = g_ax4[v];
        float h;
        h = fmaxf(fmaf(q.x, w1x0, fmaf(q.y, w1y0, bb0)), 0.f); a0 = fmaf(q.z, h, a0);
        h = fmaxf(fmaf(q.x, w1x1, fmaf(q.y, w1y1, bb1)), 0.f); a1 = fmaf(q.z, h, a1);
        a0 *= q.z;
        a1 *= q.z;
    }
    sT[lane * 9 + wid] = a0;
    sT[(lane + 32) * 9 + wid] = a1;
    __syncthreads();
    int base = blockIdx.x * 8;
    for (int q = t; q < 512; q += 256) {
        int c = q >> 3, j = q & 7;
        if (base + j < n) g_bufA[(size_t)c * NSTR + base + j] = sT[c * 9 + j];
    }
}

// ---------------- fused MLP v2: occupancy-oriented --------------------------------
// 256 threads, 128-node tile, SINGLE tile buffer reused in place (GEMM1 reads all
// of sT before relu overwrites it, barrier-separated). smem 65KB -> 3 blocks/SM.
// Thread tile: 4 nodes x 8 cols, f32x2 packed FMA. Output fp8 e4m3 (dinv-prescaled).
__global__ __launch_bounds__(256, 3) void k_mlp(const float* __restrict__ W2,
                                                const float* __restrict__ b2,
                                                const float* __restrict__ W3,
                                                int n) {
    extern __shared__ float sm[];
    float* sW2 = sm;                 // 4096 floats
    float* sW3 = sm + 4096;          // 4096 floats
    float* sT  = sm + 8192;          // [64][132] tile, reused for GEMM1 in / relu out
    const int t  = threadIdx.x;
    const int cg = t & 7;            // col group: cols cg*8 .. cg*8+7
    const int ng = t >> 3;           // node group: nodes ng*4 .. ng*4+3 (0..31)

    for (int i = t; i < 1024; i += 256) {
        ((float4*)sW2)[i] = ((const float4*)W2)[i];
        ((float4*)sW3)[i] = ((const float4*)W3)[i];
    }
    u64 bias2[4];
    #pragma unroll
    for (int j = 0; j < 4; j++)
        bias2[j] = *(const u64*)(b2 + cg * 8 + 2 * j);
    __syncthreads();

    const int ntiles = (n + 127) >> 7;
    for (int tile = blockIdx.x; tile < ntiles; tile += gridDim.x) {
        const int base = tile << 7;
        // load tile (transposed source, coalesced): 2048 float4, 8 per thread
        for (int q = t; q < 2048; q += 256) {
            int c = q >> 5, v4 = (q & 31) << 2;
            float4 val;
            if (base + v4 + 3 < n) {
                val = *(const float4*)(g_bufA + (size_t)c * NSTR + base + v4);
            } else {
                const float* p = g_bufA + (size_t)c * NSTR + base + v4;
                int rem = n - base - v4;
                val.x = (rem > 0) ? p[0] : 0.f;
                val.y = (rem > 1) ? p[1] : 0.f;
                val.z = (rem > 2) ? p[2] : 0.f;
                val.w = (rem > 3) ? p[3] : 0.f;
            }
            *(float4*)(sT + c * 132 + v4) = val;
        }
        __syncthreads();

        // GEMM1: acc = t2 @ W2 + b2   (4 nodes x 4 col-pairs per thread)
        u64 acc[4][4];
        #pragma unroll
        for (int i = 0; i < 4; i++)
            #pragma unroll
            for (int j = 0; j < 4; j++) acc[i][j] = bias2[j];
        #pragma unroll 8
        for (int k = 0; k < 64; k++) {
            float4 h = *(const float4*)(sT + k * 132 + ng * 4);
            u64 hh[4];
            hh[0] = pack2(h.x, h.x); hh[1] = pack2(h.y, h.y);
            hh[2] = pack2(h.z, h.z); hh[3] = pack2(h.w, h.w);
            #pragma unroll
            for (int j = 0; j < 4; j++) {
                u64 w = *(const u64*)(sW2 + k * 64 + cg * 8 + 2 * j);
                #pragma unroll
                for (int i = 0; i < 4; i++) fma2(acc[i][j], hh[i], w, acc[i][j]);
            }
        }
        __syncthreads();          // ALL GEMM1 reads of sT complete

        // relu -> sT (in place, k-major)
        #pragma unroll
        for (int j = 0; j < 4; j++) {
            float lo[4], hi[4];
            #pragma unroll
            for (int i = 0; i < 4; i++) {
                float a, b; unpack2(acc[i][j], a, b);
                lo[i] = fmaxf(a, 0.f); hi[i] = fmaxf(b, 0.f);
            }
            int c0 = cg * 8 + 2 * j, c1 = c0 + 1;
            *(float4*)(sT + c0 * 132 + ng * 4) = make_float4(lo[0], lo[1], lo[2], lo[3]);
            *(float4*)(sT + c1 * 132 + ng * 4) = make_float4(hi[0], hi[1], hi[2], hi[3]);
        }
        __syncthreads();

        // GEMM2: g2 = h2 @ W3 ; epilogue: * dinv[node] -> fp8 e4m3
        u64 acc2[4][4];
        #pragma unroll
        for (int i = 0; i < 4; i++)
            #pragma unroll
            for (int j = 0; j < 4; j++) acc2[i][j] = 0ull;
        #pragma unroll 8
        for (int k = 0; k < 64; k++) {
            float4 h = *(const float4*)(sT + k * 132 + ng * 4);
            u64 hh[4];
            hh[0] = pack2(h.x, h.x); hh[1] = pack2(h.y, h.y);
            hh[2] = pack2(h.z, h.z); hh[3] = pack2(h.w, h.w);
            #pragma unroll
            for (int j = 0; j < 4; j++) {
                u64 w = *(const u64*)(sW3 + k * 64 + cg * 8 + 2 * j);
                #pragma unroll
                for (int i = 0; i < 4; i++) fma2(acc2[i][j], hh[i], w, acc2[i][j]);
            }
        }
        #pragma unroll
        for (int i = 0; i < 4; i++) {
            int node = base + ng * 4 + i;
            if (node < n) {
                float dv = __ldg(&g_dinv[node]);
                unsigned short r[4];
                #pragma unroll
                for (int j = 0; j < 4; j++) {
                    float a, b; unpack2(acc2[i][j], a, b);
                    r[j] = fp8pack2(a * dv, b * dv);
                }
                uint2 val;
                val.x = (unsigned)r[0] | ((unsigned)r[1] << 16);
                val.y = (unsigned)r[2] | ((unsigned)r[3] << 16);
                *(uint2*)(g_buf8 + (size_t)node * 64 + cg * 8) = val;
            }
        }
        __syncthreads();          // GEMM2 reads done before next tile load
    }
}

// ---------------- layer 3 aggregation: h3 = dinv*(sum g2s_fp8) + b3 --------------
__global__ void k_agg64(const float* __restrict__ b3, int n) {
    int t = threadIdx.x;
    int w = (blockIdx.x * blockDim.x + t) >> 5;
    int lane = t & 31;
    int half = lane >> 4, l16 = lane & 15;
    if (w >= n) return;
    int st = g_off[w], en = g_off[w + 1];
    float4 a = make_float4(0.f, 0.f, 0.f, 0.f);
    int j = st + half;
    int s = (j < en) ? __ldg(&g_csrc[j]) : 0;
    while (j < en) {
        int jn = j + 2;
        int sn = (jn < en) ? __ldg(&g_csrc[jn]) : 0;
        unsigned u = *(const unsigned*)(g_buf8 + (size_t)s * 64 + l16 * 4);
        float2 f01 = fp8unpack2((unsigned short)(u & 0xffffu));
        float2 f23 = fp8unpack2((unsigned short)(u >> 16));
        a.x += f01.x; a.y += f01.y; a.z += f23.x; a.w += f23.y;
        s = sn; j = jn;
    }
    if (half == 0) {
        unsigned u = *(const unsigned*)(g_buf8 + (size_t)w * 64 + l16 * 4);  // self
        float2 f01 = fp8unpack2((unsigned short)(u & 0xffffu));
        float2 f23 = fp8unpack2((unsigned short)(u >> 16));
        a.x += f01.x; a.y += f01.y; a.z += f23.x; a.w += f23.y;
    }
    a.x += __shfl_xor_sync(0xffffffffu, a.x, 16);
    a.y += __shfl_xor_sync(0xffffffffu, a.y, 16);
    a.z += __shfl_xor_sync(0xffffffffu, a.z, 16);
    a.w += __shfl_xor_sync(0xffffffffu, a.w, 16);
    if (half == 0) {
        float dv = g_dinv[w];
        float4 bb = *(const float4*)(b3 + l16 * 4);
        a.x = fmaf(dv, a.x, bb.x); a.y = fmaf(dv, a.y, bb.y);
        a.z = fmaf(dv, a.z, bb.z); a.w = fmaf(dv, a.w, bb.w);
        *(float4*)(g_bufA + (size_t)w * 64 + l16 * 4) = a;   // h3 row-major
    }
}

// ---------------- mean pool + head (last block runs the head) ----------------
__global__ void k_poolfinal(const int* __restrict__ batch, const float* __restrict__ ge,
                            const float* __restrict__ Wl, const float* __restrict__ bl,
                            float* __restrict__ out, int n) {
    __shared__ int sb[2];
    __shared__ float red[256];
    __shared__ int s_last;
    int gid = blockIdx.x;
    int t = threadIdx.x;          // 256
    if (t < 2) {
        int target = gid + t;
        int lo = 0, hi = n;
        while (lo < hi) {
            int mid = (lo + hi) >> 1;
            if (batch[mid] < target) lo = mid + 1; else hi = mid;
        }
        sb[t] = lo;
    }
    __syncthreads();
    int s = sb[0], e = sb[1];
    int d = t & 63, str = t >> 6;
    float acc = 0.f;
    for (int nn = s + str; nn < e; nn += 4) acc += g_bufA[(size_t)nn * 64 + d];
    red[t] = acc;
    __syncthreads();
    if (t < 64) {
        float tot = red[t] + red[t + 64] + red[t + 128] + red[t + 192];
        g_pooled[gid * 64 + t] = tot / fmaxf((float)(e - s), 1.f);
    }
    __threadfence();
    if (t == 0) s_last = (atomicAdd(&g_poolctr, 1) == NGRAPH - 1);
    __syncthreads();
    if (!s_last) return;

    if (t == 0) g_poolctr = 0;
    __shared__ float sW[128 * NCLS];
    __shared__ float sbv[NCLS];
    for (int i = t; i < 128 * NCLS; i += 256) sW[i] = Wl[i];
    if (t < NCLS) sbv[t] = bl[t];
    __syncthreads();
    if (t < 128) {
        int g = t;
        float z[NCLS];
        #pragma unroll
        for (int c = 0; c < NCLS; c++) z[c] = sbv[c];
        for (int k = 0; k < 64; k++) {
            float p = g_pooled[g * HDIM + k];
            #pragma unroll
            for (int c = 0; c < NCLS; c++) z[c] = fmaf(p, sW[k * NCLS + c], z[c]);
        }
        for (int k = 0; k < 64; k++) {
            float p = ge[g * 64 + k];
            #pragma unroll
            for (int c = 0; c < NCLS; c++) z[c] = fmaf(p, sW[(64 + k) * NCLS + c], z[c]);
        }
        float m = z[0];
        #pragma unroll
        for (int c = 1; c < NCLS; c++) m = fmaxf(m, z[c]);
        float sum = 0.f;
        #pragma unroll
        for (int c = 0; c < NCLS; c++) sum += expf(z[c] - m);
        float l = m + logf(sum);
        #pragma unroll
        for (int c = 0; c < NCLS; c++) out[g * NCLS + c] = z[c] - l;
    }
}

// ---------------- launch ----------------
extern "C" void kernel_launch(void* const* d_in, const int* in_sizes, int n_in,
                              void* d_out, int out_size) {
    const float* x     = (const float*)d_in[0];
    const int*   ei    = (const int*)d_in[1];
    const int*   batch = (const int*)d_in[2];
    const float* ge    = (const float*)d_in[3];
    const float* W1    = (const float*)d_in[4];
    const float* b1    = (const float*)d_in[5];
    const float* W2    = (const float*)d_in[6];
    const float* b2    = (const float*)d_in[7];
    const float* W3    = (const float*)d_in[8];
    const float* b3    = (const float*)d_in[9];
    const float* Wl    = (const float*)d_in[10];
    const float* bl    = (const float*)d_in[11];
    float* out = (float*)d_out;

    int n = in_sizes[0] / 2;       // x is [N,2]
    int e = in_sizes[1] / 2;       // edge_index is [2,E]
    int vec4 = ((e & 3) == 0) ? 1 : 0;

    static const int mlp_smem = (4096 + 4096 + 64 * 132) * (int)sizeof(float);
    cudaFuncSetAttribute(k_mlp, cudaFuncAttributeMaxDynamicSharedMemorySize, mlp_smem);

    k_csr    <<<NBLK, NTHR>>>(x, ei, n, e, vec4);        // 0 (count+scan+scatter)
    k_agg2   <<<(n + 127) / 128, 128>>>(n);              // 1
    k_l2agg  <<<(n + 7) / 8, 256>>>(W1, b1, n);          // 2
    k_mlp    <<<444, 256, mlp_smem>>>(W2, b2, W3, n);    // 3  <- profiled slot
    k_agg64  <<<(n + 7) / 8, 256>>>(b3, n);              // 4
    k_poolfinal<<<NGRAPH, 256>>>(batch, ge, Wl, bl, out, n); // 5
}

// round 14
// speedup vs baseline: 1.4471x; 1.4471x over previous
#include <cuda_runtime.h>
#include <cuda_bf16.h>
#include <cuda_fp16.h>
#include <cstdint>
#include <math.h>

#define NMAX   100000
#define EMAX   1000000
#define HDIM   64
#define NGRAPH 128
#define NCLS   5
#define NTILES ((NMAX + 127) / 128)     // 782

typedef unsigned long long u64;

// ---------------- scratch (device globals; never passed from host) ----------------
__device__ int    g_deg[NMAX];
__device__ int    g_cursor[NMAX];
__device__ int    g_off[NMAX + 1];
__device__ int    g_flag[128];
__device__ int    g_poolctr;
__device__ float  g_dinv[NMAX];
__device__ int    g_csrc[EMAX];
__device__ __align__(16) float  g_xs[NMAX * 2];
__device__ __align__(16) float4 g_ax4[NMAX];
__device__ __align__(16) unsigned char g_bf[(size_t)NTILES * 16384];   // t2 bf16, plain row-major 128-node tiles
__device__ __align__(16) unsigned char g_buf8[(size_t)NMAX * HDIM];    // g2s fp8 e4m3
__device__ __align__(16) float  g_h3[(size_t)NMAX * HDIM];
__device__ __align__(16) float  g_pooled[NGRAPH * HDIM];

// ---------------- helpers ----------------
__device__ __forceinline__ unsigned bf16pack(float lo, float hi) {
    unsigned r; asm("cvt.rn.bf16x2.f32 %0, %1, %2;" : "=r"(r) : "f"(hi), "f"(lo)); return r;
}
__device__ __forceinline__ unsigned short fp8pack2(float lo, float hi) {
    unsigned short r;
    asm("cvt.rn.satfinite.e4m3x2.f32 %0, %1, %2;" : "=h"(r) : "f"(hi), "f"(lo));
    return r;
}
__device__ __forceinline__ float2 fp8unpack2(unsigned short v) {
    unsigned h2;
    asm("cvt.rn.f16x2.e4m3x2 %0, %1;" : "=r"(h2) : "h"(v));
    return __half22float2(*(__half2*)&h2);
}
__device__ __forceinline__ uint32_t smem_u32(const void* p) {
    uint32_t a;
    asm("{ .reg .u64 t; cvta.to.shared.u64 t, %1; cvt.u32.u64 %0, t; }" : "=r"(a) : "l"(p));
    return a;
}
__device__ __forceinline__ float bf16resid(float x) {
    return x - __bfloat162float(__float2bfloat16(x));
}
// mma.sync m16n8k16 bf16 (row.col), f32 accumulate in place
__device__ __forceinline__ void mma_bf16(float* d, const unsigned* a, unsigned b0, unsigned b1) {
    asm volatile(
        "mma.sync.aligned.m16n8k16.row.col.f32.bf16.bf16.f32 "
        "{%0,%1,%2,%3}, {%4,%5,%6,%7}, {%8,%9}, {%0,%1,%2,%3};"
        : "+f"(d[0]), "+f"(d[1]), "+f"(d[2]), "+f"(d[3])
        : "r"(a[0]), "r"(a[1]), "r"(a[2]), "r"(a[3]), "r"(b0), "r"(b1));
}
__device__ __forceinline__ void ldmatrix4(unsigned* r, uint32_t addr) {
    asm volatile("ldmatrix.sync.aligned.m8n8.x4.shared.b16 {%0,%1,%2,%3}, [%4];"
        : "=r"(r[0]), "=r"(r[1]), "=r"(r[2]), "=r"(r[3]) : "r"(addr));
}

// ---------------- CSR build (R8-validated) ----------------
__global__ void k_count(const int* __restrict__ dst, int e) {
    if (blockIdx.x == 0 && threadIdx.x < 128) g_flag[threadIdx.x] = 0;
    int i = blockIdx.x * blockDim.x + threadIdx.x;
    if (i < e) atomicAdd(&g_deg[dst[i]], 1);
}

__global__ void k_scan(const float* __restrict__ x, int n) {
    int b = blockIdx.x;
    int i = (b << 10) + threadIdx.x;
    int v = (i < n) ? g_deg[i] : 0;
    float dv = rsqrtf((float)(v + 1));
    if (i < n) {
        g_deg[i] = 0;
        g_dinv[i] = dv;
        float2 xv = *(const float2*)(x + 2 * i);
        g_xs[2 * i]     = dv * xv.x;
        g_xs[2 * i + 1] = dv * xv.y;
    }
    int lane = threadIdx.x & 31, wid = threadIdx.x >> 5;
    int xacc = v;
    #pragma unroll
    for (int o = 1; o < 32; o <<= 1) {
        int y = __shfl_up_sync(0xffffffffu, xacc, o);
        if (lane >= o) xacc += y;
    }
    __shared__ int ws[32];
    __shared__ int s_prefix;
    if (lane == 31) ws[wid] = xacc;
    __syncthreads();
    if (wid == 0) {
        int s = ws[lane];
        #pragma unroll
        for (int o = 1; o < 32; o <<= 1) {
            int y = __shfl_up_sync(0xffffffffu, s, o);
            if (lane >= o) s += y;
        }
        ws[lane] = s;
    }
    __syncthreads();
    int warpoff = (wid == 0) ? 0 : ws[wid - 1];
    int total = ws[31];
    if (threadIdx.x == 0) atomicExch(&g_flag[b], (int)(0x80000000u | (unsigned)total));
    if (threadIdx.x < 32) {
        int sum = 0;
        for (int p = b - 1 - (int)threadIdx.x; p >= 0; p -= 32) {
            int f;
            do { f = atomicAdd(&g_flag[p], 0); } while (f >= 0);
            sum += f & 0x7fffffff;
        }
        #pragma unroll
        for (int o = 16; o; o >>= 1) sum += __shfl_xor_sync(0xffffffffu, sum, o);
        if (threadIdx.x == 0) s_prefix = sum;
    }
    __syncthreads();
    if (i < n) {
        int off = s_prefix + warpoff + xacc - v;
        g_off[i] = off;
        g_cursor[i] = off;
        if (i == n - 1) g_off[n] = s_prefix + warpoff + xacc;
    }
}

__global__ void k_scatter4(const int* __restrict__ ei, int e) {
    int i4 = (blockIdx.x * blockDim.x + threadIdx.x) << 2;
    if (i4 >= e) return;
    if (i4 + 3 < e) {
        int4 s = *(const int4*)(ei + i4);
        int4 d = *(const int4*)(ei + e + i4);
        int p0 = atomicAdd(&g_cursor[d.x], 1);
        int p1 = atomicAdd(&g_cursor[d.y], 1);
        int p2 = atomicAdd(&g_cursor[d.z], 1);
        int p3 = atomicAdd(&g_cursor[d.w], 1);
        g_csrc[p0] = s.x; g_csrc[p1] = s.y;
        g_csrc[p2] = s.z; g_csrc[p3] = s.w;
    } else {
        for (int i = i4; i < e; i++) {
            int s = ei[i], d = ei[e + i];
            int p = atomicAdd(&g_cursor[d], 1);
            g_csrc[p] = s;
        }
    }
}
__global__ void k_scatter1(const int* __restrict__ ei, int e) {
    int i = blockIdx.x * blockDim.x + threadIdx.x;
    if (i >= e) return;
    int s = ei[i], d = ei[e + i];
    int p = atomicAdd(&g_cursor[d], 1);
    g_csrc[p] = s;
}

// ---------------- layer 1 ----------------
__global__ void k_agg2(int n) {
    int v = blockIdx.x * blockDim.x + threadIdx.x;
    if (v >= n) return;
    int st = g_off[v], en = g_off[v + 1];
    float ax = 0.f, ay = 0.f;
    for (int j = st; j < en; j += 4) {
        int rem = en - j;
        int s0 = __ldg(&g_csrc[j]);
        int s1 = (rem > 1) ? __ldg(&g_csrc[j + 1]) : s0;
        int s2 = (rem > 2) ? __ldg(&g_csrc[j + 2]) : s0;
        int s3 = (rem > 3) ? __ldg(&g_csrc[j + 3]) : s0;
        float2 x0 = *(const float2*)(g_xs + 2 * s0);
        float2 x1 = *(const float2*)(g_xs + 2 * s1);
        float2 x2 = *(const float2*)(g_xs + 2 * s2);
        float2 x3 = *(const float2*)(g_xs + 2 * s3);
        float m1 = (rem > 1) ? 1.f : 0.f;
        float m2 = (rem > 2) ? 1.f : 0.f;
        float m3 = (rem > 3) ? 1.f : 0.f;
        ax += x0.x; ay += x0.y;
        ax = fmaf(m1, x1.x, ax); ay = fmaf(m1, x1.y, ay);
        ax = fmaf(m2, x2.x, ax); ay = fmaf(m2, x2.y, ay);
        ax = fmaf(m3, x3.x, ax); ay = fmaf(m3, x3.y, ay);
    }
    float dv = g_dinv[v];
    ax += g_xs[2 * v];
    ay += g_xs[2 * v + 1];
    float4 o; o.x = dv * ax; o.y = dv * ay; o.z = dv; o.w = 0.f;
    g_ax4[v] = o;
}

// ---------------- layer 2 agg + lin1 -> bf16 plain row-major tiles ----------------
__global__ void k_l2agg(const float* __restrict__ W1, const float* __restrict__ b1, int n) {
    __shared__ float sT[64 * 9];
    int t = threadIdx.x, wid = t >> 5, lane = t & 31;
    int v = blockIdx.x * 8 + wid;
    float w1x0 = W1[lane],      w1y0 = W1[64 + lane],  bb0 = b1[lane];
    float w1x1 = W1[lane + 32], w1y1 = W1[96 + lane],  bb1 = b1[lane + 32];
    float a0 = 0.f, a1 = 0.f;
    if (v < n) {
        int st = g_off[v], en = g_off[v + 1];
        for (int j = st; j < en; j += 4) {
            int rem = en - j;
            int s0 = __ldg(&g_csrc[j]);
            int s1 = (rem > 1) ? __ldg(&g_csrc[j + 1]) : s0;
            int s2 = (rem > 2) ? __ldg(&g_csrc[j + 2]) : s0;
            int s3 = (rem > 3) ? __ldg(&g_csrc[j + 3]) : s0;
            float4 q0 = g_ax4[s0];
            float4 q1 = g_ax4[s1];
            float4 q2 = g_ax4[s2];
            float4 q3 = g_ax4[s3];
            float m1 = (rem > 1) ? 1.f : 0.f;
            float m2 = (rem > 2) ? 1.f : 0.f;
            float m3 = (rem > 3) ? 1.f : 0.f;
            float h;
            h = fmaxf(fmaf(q0.x, w1x0, fmaf(q0.y, w1y0, bb0)), 0.f); a0 = fmaf(q0.z, h, a0);
            h = fmaxf(fmaf(q0.x, w1x1, fmaf(q0.y, w1y1, bb1)), 0.f); a1 = fmaf(q0.z, h, a1);
            h = fmaxf(fmaf(q1.x, w1x0, fmaf(q1.y, w1y0, bb0)), 0.f); a0 = fmaf(m1 * q1.z, h, a0);
            h = fmaxf(fmaf(q1.x, w1x1, fmaf(q1.y, w1y1, bb1)), 0.f); a1 = fmaf(m1 * q1.z, h, a1);
            h = fmaxf(fmaf(q2.x, w1x0, fmaf(q2.y, w1y0, bb0)), 0.f); a0 = fmaf(m2 * q2.z, h, a0);
            h = fmaxf(fmaf(q2.x, w1x1, fmaf(q2.y, w1y1, bb1)), 0.f); a1 = fmaf(m2 * q2.z, h, a1);
            h = fmaxf(fmaf(q3.x, w1x0, fmaf(q3.y, w1y0, bb0)), 0.f); a0 = fmaf(m3 * q3.z, h, a0);
            h = fmaxf(fmaf(q3.x, w1x1, fmaf(q3.y, w1y1, bb1)), 0.f); a1 = fmaf(m3 * q3.z, h, a1);
        }
        float4 q = g_ax4[v];
        float h;
        h = fmaxf(fmaf(q.x, w1x0, fmaf(q.y, w1y0, bb0)), 0.f); a0 = fmaf(q.z, h, a0);
        h = fmaxf(fmaf(q.x, w1x1, fmaf(q.y, w1y1, bb1)), 0.f); a1 = fmaf(q.z, h, a1);
        a0 *= q.z;
        a1 *= q.z;
    }
    sT[lane * 9 + wid] = a0;
    sT[(lane + 32) * 9 + wid] = a1;
    __syncthreads();
    // emit 8 node-rows as bf16, plain row-major tile layout
    if (t < 64) {
        int j = t >> 3, ch = t & 7;
        int v2 = blockIdx.x * 8 + j;
        if (v2 < n) {
            int tile = v2 >> 7, r = v2 & 127;
            uint4 u;
            u.x = bf16pack(sT[(ch*8+0)*9 + j], sT[(ch*8+1)*9 + j]);
            u.y = bf16pack(sT[(ch*8+2)*9 + j], sT[(ch*8+3)*9 + j]);
            u.z = bf16pack(sT[(ch*8+4)*9 + j], sT[(ch*8+5)*9 + j]);
            u.w = bf16pack(sT[(ch*8+6)*9 + j], sT[(ch*8+7)*9 + j]);
            *(uint4*)(g_bf + (size_t)tile * 16384 + r * 128 + ch * 16) = u;
        }
    }
}

// ---------------- mma.sync MLP: g2s = dinv*(relu(t2@W2+b2)@W3) -> fp8 ------------
// 256 threads, 128-node tiles, warp w owns rows [16w,16w+16).
// Weight fragments precomputed per-lane into smem (hi + bf16-residual lo).
// GEMM1 acc (f32 frag) -> relu+bias -> bf16 A-frag for GEMM2 IN REGISTERS.
__global__ __launch_bounds__(256, 2) void k_mlp(const float* __restrict__ W2,
                                                const float* __restrict__ b2,
                                                const float* __restrict__ W3,
                                                int n) {
    extern __shared__ char sm[];
    u64*  bfr = (u64*)sm;                  // [4 variants][4 ksteps][8 nblocks][32 lanes]  32KB
    char* At  = sm + 32768;                // A tile: 128 rows x 144B stride               18KB
    const int t = threadIdx.x, lane = t & 31, w = t >> 5;

    // ---- precompute weight fragments: v0=W2hi v1=W2lo v2=W3hi v3=W3lo ----
    for (int fg = w; fg < 128; fg += 8) {
        int v  = fg >> 5;
        int ks = (fg >> 3) & 3;
        int nb = fg & 7;
        const float* W = (v < 2) ? W2 : W3;
        int nn = nb * 8 + (lane >> 2);
        int k0 = ks * 16 + (lane & 3) * 2;
        float w00 = __ldg(&W[k0 * 64 + nn]);
        float w01 = __ldg(&W[(k0 + 1) * 64 + nn]);
        float w08 = __ldg(&W[(k0 + 8) * 64 + nn]);
        float w09 = __ldg(&W[(k0 + 9) * 64 + nn]);
        unsigned b0, b1;
        if (v & 1) {
            b0 = bf16pack(bf16resid(w00), bf16resid(w01));
            b1 = bf16pack(bf16resid(w08), bf16resid(w09));
        } else {
            b0 = bf16pack(w00, w01);
            b1 = bf16pack(w08, w09);
        }
        bfr[fg * 32 + lane] = ((u64)b1 << 32) | (u64)b0;
    }
    // per-lane b2 pairs: cols nb*8 + (lane&3)*2 + {0,1}
    float2 b2p[8];
    #pragma unroll
    for (int nb = 0; nb < 8; nb++) {
        int c = nb * 8 + (lane & 3) * 2;
        b2p[nb] = make_float2(__ldg(&b2[c]), __ldg(&b2[c + 1]));
    }
    __syncthreads();

    const uint32_t at_base = smem_u32(At);
    const int ntiles = (n + 127) >> 7;
    for (int tile = blockIdx.x; tile < ntiles; tile += gridDim.x) {
        const int base = tile << 7;
        // load A tile: gmem 128B rows -> smem 144B stride (conflict-free ldmatrix)
        for (int q = t; q < 1024; q += 256) {
            int r = q >> 3, p = q & 7;
            uint4 val = *(const uint4*)(g_bf + (size_t)tile * 16384 + r * 128 + p * 16);
            *(uint4*)(At + r * 144 + p * 16) = val;
        }
        __syncthreads();

        // A fragments: 4 ksteps x ldmatrix.x4
        unsigned aF[4][4];
        uint32_t arow = at_base + (w * 16 + (lane & 15)) * 144 + (lane >> 4) * 16;
        #pragma unroll
        for (int ks = 0; ks < 4; ks++) ldmatrix4(aF[ks], arow + ks * 32);
        __syncthreads();    // A tile consumed; next iteration may overwrite

        // ---- GEMM1: D1 = A @ W2 (hi + lo) ----
        float acc[8][4];
        #pragma unroll
        for (int nb = 0; nb < 8; nb++)
            #pragma unroll
            for (int i = 0; i < 4; i++) acc[nb][i] = 0.f;
        #pragma unroll
        for (int ks = 0; ks < 4; ks++) {
            #pragma unroll
            for (int nb = 0; nb < 8; nb++) {
                u64 fh = bfr[((0 * 4 + ks) * 8 + nb) * 32 + lane];
                mma_bf16(acc[nb], aF[ks], (unsigned)fh, (unsigned)(fh >> 32));
                u64 fl = bfr[((1 * 4 + ks) * 8 + nb) * 32 + lane];
                mma_bf16(acc[nb], aF[ks], (unsigned)fl, (unsigned)(fl >> 32));
            }
        }

        // ---- epilogue 1 (in regs): +b2, relu, bf16 -> A2 fragments ----
        unsigned a2[4][4];
        #pragma unroll
        for (int j = 0; j < 4; j++) {
            int n0 = 2 * j, n1 = 2 * j + 1;
            a2[j][0] = bf16pack(fmaxf(acc[n0][0] + b2p[n0].x, 0.f),
                                fmaxf(acc[n0][1] + b2p[n0].y, 0.f));
            a2[j][1] = bf16pack(fmaxf(acc[n0][2] + b2p[n0].x, 0.f),
                                fmaxf(acc[n0][3] + b2p[n0].y, 0.f));
            a2[j][2] = bf16pack(fmaxf(acc[n1][0] + b2p[n1].x, 0.f),
                                fmaxf(acc[n1][1] + b2p[n1].y, 0.f));
            a2[j][3] = bf16pack(fmaxf(acc[n1][2] + b2p[n1].x, 0.f),
                                fmaxf(acc[n1][3] + b2p[n1].y, 0.f));
        }

        // ---- GEMM2: D2 = A2 @ W3 (hi + lo) ----
        float acc2[8][4];
        #pragma unroll
        for (int nb = 0; nb < 8; nb++)
            #pragma unroll
            for (int i = 0; i < 4; i++) acc2[nb][i] = 0.f;
        #pragma unroll
        for (int ks = 0; ks < 4; ks++) {
            #pragma unroll
            for (int nb = 0; nb < 8; nb++) {
                u64 fh = bfr[((2 * 4 + ks) * 8 + nb) * 32 + lane];
                mma_bf16(acc2[nb], a2[ks], (unsigned)fh, (unsigned)(fh >> 32));
                u64 fl = bfr[((3 * 4 + ks) * 8 + nb) * 32 + lane];
                mma_bf16(acc2[nb], a2[ks], (unsigned)fl, (unsigned)(fl >> 32));
            }
        }

        // ---- epilogue 2: * dinv -> fp8 stores ----
        int r0 = base + w * 16 + (lane >> 2);
        int r1 = r0 + 8;
        float dv0 = (r0 < n) ? __ldg(&g_dinv[r0]) : 0.f;
        float dv1 = (r1 < n) ? __ldg(&g_dinv[r1]) : 0.f;
        int coff = (lane & 3) * 2;
        #pragma unroll
        for (int nb = 0; nb < 8; nb++) {
            unsigned short v0 = fp8pack2(acc2[nb][0] * dv0, acc2[nb][1] * dv0);
            unsigned short v1 = fp8pack2(acc2[nb][2] * dv1, acc2[nb][3] * dv1);
            if (r0 < n) *(unsigned short*)(g_buf8 + (size_t)r0 * 64 + nb * 8 + coff) = v0;
            if (r1 < n) *(unsigned short*)(g_buf8 + (size_t)r1 * 64 + nb * 8 + coff) = v1;
        }
    }
}

// ---------------- layer 3 aggregation (fp8 gathers) ----------------
__global__ void k_agg64(const float* __restrict__ b3, int n) {
    int t = threadIdx.x;
    int w = (blockIdx.x * blockDim.x + t) >> 5;
    int lane = t & 31;
    int half = lane >> 4, l16 = lane & 15;
    if (w >= n) return;
    int st = g_off[w], en = g_off[w + 1];
    float4 a = make_float4(0.f, 0.f, 0.f, 0.f);
    int j = st + half;
    int s = (j < en) ? __ldg(&g_csrc[j]) : 0;
    while (j < en) {
        int jn = j + 2;
        int sn = (jn < en) ? __ldg(&g_csrc[jn]) : 0;
        unsigned u = *(const unsigned*)(g_buf8 + (size_t)s * 64 + l16 * 4);
        float2 f01 = fp8unpack2((unsigned short)(u & 0xffffu));
        float2 f23 = fp8unpack2((unsigned short)(u >> 16));
        a.x += f01.x; a.y += f01.y; a.z += f23.x; a.w += f23.y;
        s = sn; j = jn;
    }
    if (half == 0) {
        unsigned u = *(const unsigned*)(g_buf8 + (size_t)w * 64 + l16 * 4);
        float2 f01 = fp8unpack2((unsigned short)(u & 0xffffu));
        float2 f23 = fp8unpack2((unsigned short)(u >> 16));
        a.x += f01.x; a.y += f01.y; a.z += f23.x; a.w += f23.y;
    }
    a.x += __shfl_xor_sync(0xffffffffu, a.x, 16);
    a.y += __shfl_xor_sync(0xffffffffu, a.y, 16);
    a.z += __shfl_xor_sync(0xffffffffu, a.z, 16);
    a.w += __shfl_xor_sync(0xffffffffu, a.w, 16);
    if (half == 0) {
        float dv = g_dinv[w];
        float4 bb = *(const float4*)(b3 + l16 * 4);
        a.x = fmaf(dv, a.x, bb.x); a.y = fmaf(dv, a.y, bb.y);
        a.z = fmaf(dv, a.z, bb.z); a.w = fmaf(dv, a.w, bb.w);
        *(float4*)(g_h3 + (size_t)w * 64 + l16 * 4) = a;
    }
}

// ---------------- mean pool + head ----------------
__global__ void k_poolfinal(const int* __restrict__ batch, const float* __restrict__ ge,
                            const float* __restrict__ Wl, const float* __restrict__ bl,
                            float* __restrict__ out, int n) {
    __shared__ int sb[2];
    __shared__ float red[256];
    __shared__ int s_last;
    int gid = blockIdx.x;
    int t = threadIdx.x;
    if (t < 2) {
        int target = gid + t;
        int lo = 0, hi = n;
        while (lo < hi) {
            int mid = (lo + hi) >> 1;
            if (batch[mid] < target) lo = mid + 1; else hi = mid;
        }
        sb[t] = lo;
    }
    __syncthreads();
    int s = sb[0], e = sb[1];
    int d = t & 63, str = t >> 6;
    float acc = 0.f;
    for (int nn = s + str; nn < e; nn += 4) acc += g_h3[(size_t)nn * 64 + d];
    red[t] = acc;
    __syncthreads();
    if (t < 64) {
        float tot = red[t] + red[t + 64] + red[t + 128] + red[t + 192];
        g_pooled[gid * 64 + t] = tot / fmaxf((float)(e - s), 1.f);
    }
    __threadfence();
    if (t == 0) s_last = (atomicAdd(&g_poolctr, 1) == NGRAPH - 1);
    __syncthreads();
    if (!s_last) return;

    if (t == 0) g_poolctr = 0;
    __shared__ float sW[128 * NCLS];
    __shared__ float sbv[NCLS];
    for (int i = t; i < 128 * NCLS; i += 256) sW[i] = Wl[i];
    if (t < NCLS) sbv[t] = bl[t];
    __syncthreads();
    if (t < 128) {
        int g = t;
        float z[NCLS];
        #pragma unroll
        for (int c = 0; c < NCLS; c++) z[c] = sbv[c];
        for (int k = 0; k < 64; k++) {
            float p = g_pooled[g * HDIM + k];
            #pragma unroll
            for (int c = 0; c < NCLS; c++) z[c] = fmaf(p, sW[k * NCLS + c], z[c]);
        }
        for (int k = 0; k < 64; k++) {
            float p = ge[g * 64 + k];
            #pragma unroll
            for (int c = 0; c < NCLS; c++) z[c] = fmaf(p, sW[(64 + k) * NCLS + c], z[c]);
        }
        float m = z[0];
        #pragma unroll
        for (int c = 1; c < NCLS; c++) m = fmaxf(m, z[c]);
        float sum = 0.f;
        #pragma unroll
        for (int c = 0; c < NCLS; c++) sum += expf(z[c] - m);
        float l = m + logf(sum);
        #pragma unroll
        for (int c = 0; c < NCLS; c++) out[g * NCLS + c] = z[c] - l;
    }
}

// ---------------- launch ----------------
extern "C" void kernel_launch(void* const* d_in, const int* in_sizes, int n_in,
                              void* d_out, int out_size) {
    const float* x     = (const float*)d_in[0];
    const int*   ei    = (const int*)d_in[1];
    const int*   batch = (const int*)d_in[2];
    const float* ge    = (const float*)d_in[3];
    const float* W1    = (const float*)d_in[4];
    const float* b1    = (const float*)d_in[5];
    const float* W2    = (const float*)d_in[6];
    const float* b2    = (const float*)d_in[7];
    const float* W3    = (const float*)d_in[8];
    const float* b3    = (const float*)d_in[9];
    const float* Wl    = (const float*)d_in[10];
    const float* bl    = (const float*)d_in[11];
    float* out = (float*)d_out;

    int n  = in_sizes[0] / 2;
    int e  = in_sizes[1] / 2;
    int nb = (n + 1023) / 1024;

    static const int mlp_smem = 32768 + 128 * 144;   // 51200 B
    cudaFuncSetAttribute(k_mlp, cudaFuncAttributeMaxDynamicSharedMemorySize, mlp_smem);

    k_count  <<<(e + 255) / 256, 256>>>(ei + e, e);      // 0
    k_scan   <<<nb, 1024>>>(x, n);                       // 1
    if ((e & 3) == 0)
        k_scatter4<<<((e >> 2) + 255) / 256, 256>>>(ei, e);  // 2
    else
        k_scatter1<<<(e + 255) / 256, 256>>>(ei, e);
    k_agg2   <<<(n + 127) / 128, 128>>>(n);              // 3
    k_l2agg  <<<(n + 7) / 8, 256>>>(W1, b1, n);          // 4
    k_mlp    <<<296, 256, mlp_smem>>>(W2, b2, W3, n);    // 5  mma.sync tensor cores
    k_agg64  <<<(n + 7) / 8, 256>>>(b3, n);              // 6
    k_poolfinal<<<NGRAPH, 256>>>(batch, ge, Wl, bl, out, n); // 7
}